// round 11
// baseline (speedup 1.0000x reference)
#include <cuda_runtime.h>

// LIF, exact k=4 renewal-group folding — overhead-reduced revision of R10.
//
// Exact step: f = set.le(S,th); S = fma(S,f,x)  (bit-exact, proven R4..R10).
// Group of 4 steps (entry S, inputs x1..x4):
//   u1=S+x1; u2=u1+x2; u3=u2+x3                 speculative no-spike FADDs
//   a  = fma(u3, [u3<=th], x4)                  exact step-4 fold
//   r  = (m0|m1) ? (m0?T0:T1) : (m2?T2:a)       priority select TREE
// with m0=[S>th], m1=[u1>th], m2=[u2>th]; T_k = exact tail of a restart at
// position k (computed by helper warps with the exact STEPX recurrence).
// First-crossing-from-left semantics preserved exactly (same as R10).
//
// 32 blocks = 16 batches x 2 neuron-halves (32 chains). 256 threads:
//   wid4      : chain warp, 32 groups/tile (128 steps), exports group entries
//   wid5,6    : T-table helpers for tile t+1 (even/odd groups)
//   wid1,2,3,7: rd warps — replay 8 groups each of tile t-1 from entries
//               (exact STEPX), compute out/spike, store direct to global
//   wid0      : x stager (tile t+2)
// One __syncthreads per 128-step tile (256 barriers). 43KB static smem.

#define NB 16
#define NS 256
#define NH 128
#define NN 64
#define NPB 32
#define HT 128
#define NTILES 256
#define GPT 32                      // k=4 groups per tile
#define TT (NS * NH)
#define TOTE ((long long)NB * NS * NN * NH)

#define STEPX(S, XV, TH) do {                                               \
    float f_;                                                               \
    asm("set.le.f32.f32 %0, %1, %2;" : "=f"(f_) : "f"(S), "f"(TH));         \
    asm("fma.rn.f32 %0, %1, %2, %3;" : "=f"(S) : "f"(S), "f"(f_), "f"(XV)); \
} while (0)

__global__ __launch_bounds__(256, 1)
void lif_kernel(const float* __restrict__ inputs,
                const float* __restrict__ threshes,
                const float* __restrict__ acc0,
                float* __restrict__ outbuf)
{
    __shared__ float4 Tq[2][GPT][NPB];     // 32 KB  T-quads {T0,T1,T2,-}
    __shared__ float  ent[2][GPT][NPB];    //  8 KB  group-entry S
    __shared__ float  xs[4][HT];           //  2 KB  x ring (t-1,t,t+1,t+2)
    __shared__ float  thr[NPB];

    const int b    = blockIdx.x >> 1;
    const int g    = blockIdx.x & 1;
    const int tid  = threadIdx.x;
    const int wid  = tid >> 5;
    const int lane = tid & 31;
    const float* xb = inputs + (long long)b * TT;
    float* outp = outbuf;
    float* spkp = outbuf + TOTE;

    // ---- prologue 1: stage x(0), x(1); thresholds ----
    if (wid == 0)
        *(float4*)&xs[0][lane * 4] = *(const float4*)(xb + lane * 4);
    if (wid == 3)
        *(float4*)&xs[1][lane * 4] = *(const float4*)(xb + HT + lane * 4);
    if (wid == 1) thr[lane] = threshes[g * NPB + lane];
    __syncthreads();

    const float th = thr[lane];            // lane == chain index in every role

    // ---- prologue 2: T(0) by helpers; chain loads acc0 ----
    float S = 0.0f;
    if (wid == 5 || wid == 6) {
        const int par = wid - 5;
        #pragma unroll
        for (int gg = 0; gg < 16; ++gg) {
            const int grp = gg * 2 + par;
            float4 xq = *(const float4*)&xs[0][grp * 4];
            float T2 = xq.z;  STEPX(T2, xq.w, th);
            float T1 = xq.y;  STEPX(T1, xq.z, th);  STEPX(T1, xq.w, th);
            float T0 = xq.x;  STEPX(T0, xq.y, th);  STEPX(T0, xq.z, th);
            STEPX(T0, xq.w, th);
            Tq[0][grp][lane] = make_float4(T0, T1, T2, 0.0f);
        }
    }
    if (wid == 4) S = acc0[b * NN + g * NPB + lane];
    __syncthreads();

    for (int t = 0; t <= NTILES; ++t) {
        if (wid == 4) {
            // ================= chain warp: tile t =================
            if (t < NTILES) {
                const float*  __restrict__ xr = xs[t & 3];
                const float4* __restrict__ Tt = &Tq[t & 1][0][0];
                float* __restrict__ ed = &ent[t & 1][0][0];
                #pragma unroll
                for (int grp = 0; grp < GPT; ++grp) {
                    float4 xq = *(const float4*)&xr[grp * 4];   // broadcast LDS
                    float4 Tv = Tt[grp * NPB + lane];           // LDS.128
                    ed[grp * NPB + lane] = S;                   // group entry
                    float u1 = S + xq.x;
                    float u2 = u1 + xq.y;
                    float u3 = u2 + xq.z;
                    float Sn;
                    asm("{\n\t"
                        ".reg .pred m0, m01, m2;\n\t"
                        ".reg .f32  f3, a, sl, inr;\n\t"
                        "setp.gt.f32 m0, %1, %2;\n\t"        // S  > th
                        "setp.gt.or.f32 m01, %3, %2, m0;\n\t"// u1 > th | m0
                        "setp.gt.f32 m2, %4, %2;\n\t"        // u2 > th
                        "set.le.f32.f32 f3, %5, %2;\n\t"     // [u3 <= th]
                        "fma.rn.f32 a, %5, f3, %6;\n\t"      // exact step-4 fold
                        "selp.f32 sl, %7, %8, m0;\n\t"       // m0 ? T0 : T1
                        "selp.f32 inr, %9, a, m2;\n\t"       // m2 ? T2 : a
                        "selp.f32 %0, sl, inr, m01;\n\t"     // priority tree root
                        "}"
                        : "=f"(Sn)
                        : "f"(S), "f"(th), "f"(u1), "f"(u2), "f"(u3),
                          "f"(xq.w), "f"(Tv.x), "f"(Tv.y), "f"(Tv.z));
                    S = Sn;
                }
            }
        } else if (wid == 0) {
            // ================= x stager: tile t+2 =================
            if (t + 2 < NTILES)
                *(float4*)&xs[(t + 2) & 3][lane * 4] =
                    *(const float4*)(xb + (t + 2) * HT + lane * 4);
        } else if (wid == 5 || wid == 6) {
            // ================= T helpers: tile t+1 =================
            if (t + 1 < NTILES) {
                const int par = wid - 5;
                const float* __restrict__ xr = xs[(t + 1) & 3];
                float4* __restrict__ Td = &Tq[(t + 1) & 1][0][0];
                #pragma unroll
                for (int gg = 0; gg < 16; ++gg) {
                    const int grp = gg * 2 + par;
                    float4 xq = *(const float4*)&xr[grp * 4];
                    float T2 = xq.z;  STEPX(T2, xq.w, th);
                    float T1 = xq.y;  STEPX(T1, xq.z, th);  STEPX(T1, xq.w, th);
                    float T0 = xq.x;  STEPX(T0, xq.y, th);  STEPX(T0, xq.z, th);
                    STEPX(T0, xq.w, th);
                    Td[grp * NPB + lane] = make_float4(T0, T1, T2, 0.0f);
                }
            }
        } else {
            // ===== rd warps (wid 1,2,3,7): replay + store tile t-1 =====
            if (t >= 1) {
                const int r  = (wid == 7) ? 3 : (wid - 1);   // 0..3
                const int dt = t - 1;                        // == s row index
                const float* __restrict__ xr = xs[dt & 3];
                const float* __restrict__ ed = &ent[dt & 1][0][0];
                float* ob = outp + (((long long)b * NS + dt) * NN + g * NPB) * NH
                          + (long long)lane * NH;
                float* sb = ob + TOTE;
                #pragma unroll
                for (int k = 0; k < 8; ++k) {
                    const int grp = r * 8 + k;
                    float  P  = ed[grp * NPB + lane];        // group entry
                    float4 xq = *(const float4*)&xr[grp * 4];
                    float4 v;
                    STEPX(P, xq.x, th); v.x = P;
                    STEPX(P, xq.y, th); v.y = P;
                    STEPX(P, xq.z, th); v.z = P;
                    STEPX(P, xq.w, th); v.w = P;
                    float f0, f1, f2, f3;
                    asm("set.gt.f32.f32 %0, %1, %2;" : "=f"(f0) : "f"(v.x), "f"(th));
                    asm("set.gt.f32.f32 %0, %1, %2;" : "=f"(f1) : "f"(v.y), "f"(th));
                    asm("set.gt.f32.f32 %0, %1, %2;" : "=f"(f2) : "f"(v.z), "f"(th));
                    asm("set.gt.f32.f32 %0, %1, %2;" : "=f"(f3) : "f"(v.w), "f"(th));
                    float4 o  = make_float4(v.x * f0, v.y * f1, v.z * f2, v.w * f3);
                    float4 sp = make_float4(f0, f1, f2, f3);
                    *(float4*)(ob + grp * 4) = o;            // STG.128
                    *(float4*)(sb + grp * 4) = sp;
                }
            }
        }
        __syncthreads();
    }
}

extern "C" void kernel_launch(void* const* d_in, const int* in_sizes, int n_in,
                              void* d_out, int out_size)
{
    const float* inputs   = (const float*)d_in[0];  // [B,S,H]
    const float* threshes = (const float*)d_in[1];  // [N]
    const float* acc0     = (const float*)d_in[2];  // [B,N]
    float* out = (float*)d_out;                     // outs then spikes (f32)

    lif_kernel<<<NB * 2, 256>>>(inputs, threshes, acc0, out);
}

// round 12
// speedup vs baseline: 1.4131x; 1.4131x over previous
#include <cuda_runtime.h>

// LIF, exact k=4 renewal-group folding. R10 skeleton (proven 284us, coalesced
// drain) with the chain's select CASCADE replaced by a parallel select TREE.
//
// Exact step: f = set.le(S,th); S = fma(S,f,x)  (bit-exact, proven R4..R11).
// Group of 4 (entry S, inputs x1..x4):
//   u1=S+x1; u2=u1+x2; u3=u2+x3              speculative no-spike FADDs
//   a  = fma(u3, [u3<=th], x4)               exact step-4 fold
//   r  = m01 ? (m0?T0:T1) : (m2?T2:a)        priority tree (first crossing)
// m0=[S>th], m01=m0|[u1>th], m2=[u2>th]; T_k = exact restart tails computed
// by helper warps with the exact STEPX recurrence (proven R10).
//
// 32 blocks = 16 batches x 2 neuron-halves (32 chains). 256 threads:
//   wid4  : chain warp, 16 groups/tile (64 steps), exports group entries
//   wid5,6: T-table helpers for tile t+1 (even/odd groups)
//   wid1,2: rerun warps: exact per-step S of tile t-1 -> sbuf (STS.128)
//   wid3,7: drain warps: sbuf tile t-2 -> global, h-contiguous STG.128
//   wid0  : x stager (tile t+2)
// One __syncthreads per 64-step tile. ~39KB static smem.

#define NB 16
#define NS 256
#define NH 128
#define NN 64
#define NPB 32
#define HT 64
#define NTILES 512
#define GPT 16                      // k=4 groups per tile
#define RS 68                       // sbuf row stride: 16B chunk 17n+q, conflict-free
#define TT (NS * NH)
#define TOTE ((long long)NB * NS * NN * NH)

#define STEPX(S, XV, TH) do {                                               \
    float f_;                                                               \
    asm("set.le.f32.f32 %0, %1, %2;" : "=f"(f_) : "f"(S), "f"(TH));         \
    asm("fma.rn.f32 %0, %1, %2, %3;" : "=f"(S) : "f"(S), "f"(f_), "f"(XV)); \
} while (0)

__global__ __launch_bounds__(256, 1)
void lif_kernel(const float* __restrict__ inputs,
                const float* __restrict__ threshes,
                const float* __restrict__ acc0,
                float* __restrict__ outbuf)
{
    __shared__ float4 Tq[2][GPT][NPB];       // 16 KB  T-quads {T0,T1,T2,-}
    __shared__ float  ent[2][GPT][NPB];      //  4 KB  group-entry S
    __shared__ float  sbuf[2][NPB * RS];     // 17.4 KB rerun per-step S
    __shared__ float  xs[4][HT];             //  1 KB  x ring
    __shared__ float  thr[NPB];

    const int b    = blockIdx.x >> 1;
    const int g    = blockIdx.x & 1;
    const int tid  = threadIdx.x;
    const int wid  = tid >> 5;
    const int lane = tid & 31;
    const float* xb = inputs + (long long)b * TT;
    float* outp = outbuf;
    float* spkp = outbuf + TOTE;

    // ---- prologue 1: stage x(0), x(1); thresholds ----
    if (wid == 0) {
        if (lane < 16)
            *(float4*)&xs[0][lane * 4] = *(const float4*)(xb + lane * 4);
        else {
            int l = lane - 16;
            *(float4*)&xs[1][l * 4] = *(const float4*)(xb + HT + l * 4);
        }
    }
    if (wid == 1) thr[lane] = threshes[g * NPB + lane];
    __syncthreads();

    const float th = thr[lane];              // lane == chain index in all roles

    // ---- prologue 2: T(0); chain loads acc0 ----
    float S = 0.0f;
    if (wid == 5 || wid == 6) {
        const int par = wid - 5;
        #pragma unroll
        for (int gg = 0; gg < 8; ++gg) {
            const int grp = gg * 2 + par;
            float4 xq = *(const float4*)&xs[0][grp * 4];
            float T2 = xq.z;  STEPX(T2, xq.w, th);
            float T1 = xq.y;  STEPX(T1, xq.z, th);  STEPX(T1, xq.w, th);
            float T0 = xq.x;  STEPX(T0, xq.y, th);  STEPX(T0, xq.z, th);
            STEPX(T0, xq.w, th);
            Tq[0][grp][lane] = make_float4(T0, T1, T2, 0.0f);
        }
    }
    if (wid == 4) S = acc0[b * NN + g * NPB + lane];
    __syncthreads();

    for (int t = 0; t <= NTILES + 1; ++t) {
        if (wid == 4) {
            // ================= chain warp: tile t =================
            if (t < NTILES) {
                const float*  __restrict__ xr = xs[t & 3];
                const float4* __restrict__ Tt = &Tq[t & 1][0][0];
                float* __restrict__ ed = &ent[t & 1][0][0];
                #pragma unroll
                for (int grp = 0; grp < GPT; ++grp) {
                    float4 xq = *(const float4*)&xr[grp * 4];   // broadcast LDS
                    float4 Tv = Tt[grp * NPB + lane];           // LDS.128
                    ed[grp * NPB + lane] = S;                   // group entry
                    float u1 = S + xq.x;
                    float u2 = u1 + xq.y;
                    float u3 = u2 + xq.z;
                    float Sn;
                    asm("{\n\t"
                        ".reg .pred m0, m01, m2;\n\t"
                        ".reg .f32  f3, a, sl, inr;\n\t"
                        "setp.gt.f32 m0, %1, %2;\n\t"         // S  > th
                        "setp.gt.or.f32 m01, %3, %2, m0;\n\t" // u1 > th | m0
                        "setp.gt.f32 m2, %4, %2;\n\t"         // u2 > th
                        "set.le.f32.f32 f3, %5, %2;\n\t"      // [u3 <= th]
                        "fma.rn.f32 a, %5, f3, %6;\n\t"       // exact step-4 fold
                        "selp.f32 sl, %7, %8, m0;\n\t"        // m0 ? T0 : T1
                        "selp.f32 inr, %9, a, m2;\n\t"        // m2 ? T2 : a
                        "selp.f32 %0, sl, inr, m01;\n\t"      // priority root
                        "}"
                        : "=f"(Sn)
                        : "f"(S), "f"(th), "f"(u1), "f"(u2), "f"(u3),
                          "f"(xq.w), "f"(Tv.x), "f"(Tv.y), "f"(Tv.z));
                    S = Sn;
                }
            }
        } else if (wid == 0) {
            // ================= x stager: tile t+2 =================
            if (t + 2 < NTILES && lane < 16)
                *(float4*)&xs[(t + 2) & 3][lane * 4] =
                    *(const float4*)(xb + (t + 2) * HT + lane * 4);
        } else if (wid == 5 || wid == 6) {
            // ================= T helpers: tile t+1 =================
            if (t + 1 < NTILES) {
                const int par = wid - 5;
                const float* __restrict__ xr = xs[(t + 1) & 3];
                float4* __restrict__ Td = &Tq[(t + 1) & 1][0][0];
                #pragma unroll
                for (int gg = 0; gg < 8; ++gg) {
                    const int grp = gg * 2 + par;
                    float4 xq = *(const float4*)&xr[grp * 4];
                    float T2 = xq.z;  STEPX(T2, xq.w, th);
                    float T1 = xq.y;  STEPX(T1, xq.z, th);  STEPX(T1, xq.w, th);
                    float T0 = xq.x;  STEPX(T0, xq.y, th);  STEPX(T0, xq.z, th);
                    STEPX(T0, xq.w, th);
                    Td[grp * NPB + lane] = make_float4(T0, T1, T2, 0.0f);
                }
            }
        } else if (wid == 1 || wid == 2) {
            // ================= rerun warps: tile t-1 -> sbuf =================
            if (t >= 1 && t <= NTILES) {
                const int par = wid - 1;
                const int pt  = (t - 1) & 1;
                const float* __restrict__ xr  = xs[(t - 1) & 3];
                const float* __restrict__ ed  = &ent[pt][0][0];
                float* __restrict__ sb = sbuf[pt];
                #pragma unroll
                for (int gg = 0; gg < 8; ++gg) {
                    const int grp = gg * 2 + par;
                    float  P  = ed[grp * NPB + lane];
                    float4 xq = *(const float4*)&xr[grp * 4];
                    float4 o;
                    STEPX(P, xq.x, th); o.x = P;
                    STEPX(P, xq.y, th); o.y = P;
                    STEPX(P, xq.z, th); o.z = P;
                    STEPX(P, xq.w, th); o.w = P;
                    *(float4*)&sb[lane * RS + grp * 4] = o;    // STS.128
                }
            }
        } else {
            // ========== drain warps (wid 3,7): sbuf tile t-2 -> global ==========
            if (t >= 2) {
                const int dt = t - 2;
                const int pt = dt & 1;
                const int s  = dt >> 1;
                const int h0 = (dt & 1) * HT;
                const int idx0 = (wid == 7) ? 256 : 0;
                const float* __restrict__ sb = sbuf[pt];
                float* ob = outp + (((long long)b * NS + s) * NN + g * NPB) * NH + h0;
                float* sp = ob + TOTE;
                #pragma unroll
                for (int i = 0; i < 8; ++i) {
                    int idx = idx0 + i * 32 + lane;   // n = idx>>4, q = idx&15
                    int n = idx >> 4, q = idx & 15;
                    float4 v = *(const float4*)&sb[n * RS + q * 4];
                    float tn = thr[n];
                    float f0, f1, f2, f3;
                    asm("set.gt.f32.f32 %0, %1, %2;" : "=f"(f0) : "f"(v.x), "f"(tn));
                    asm("set.gt.f32.f32 %0, %1, %2;" : "=f"(f1) : "f"(v.y), "f"(tn));
                    asm("set.gt.f32.f32 %0, %1, %2;" : "=f"(f2) : "f"(v.z), "f"(tn));
                    asm("set.gt.f32.f32 %0, %1, %2;" : "=f"(f3) : "f"(v.w), "f"(tn));
                    float4 o = make_float4(v.x * f0, v.y * f1, v.z * f2, v.w * f3);
                    float4 k = make_float4(f0, f1, f2, f3);
                    *(float4*)(ob + n * NH + q * 4) = o;       // STG.128 coalesced
                    *(float4*)(sp + n * NH + q * 4) = k;
                }
            }
        }
        __syncthreads();
    }
}

extern "C" void kernel_launch(void* const* d_in, const int* in_sizes, int n_in,
                              void* d_out, int out_size)
{
    const float* inputs   = (const float*)d_in[0];  // [B,S,H]
    const float* threshes = (const float*)d_in[1];  // [N]
    const float* acc0     = (const float*)d_in[2];  // [B,N]
    float* out = (float*)d_out;                     // outs then spikes (f32)

    lif_kernel<<<NB * 2, 256>>>(inputs, threshes, acc0, out);
}

// round 14
// speedup vs baseline: 1.8946x; 1.3408x over previous
#include <cuda_runtime.h>

// LIF, exact k=4 renewal-group folding, HT=128 tiles (256 barriers), dynamic
// shared memory (77KB > 48KB static limit; set via cudaFuncSetAttribute —
// not a stream op, graph-capture safe).
//
// Exact step: f = set.le(S,th); S = fma(S,f,x)  (bit-exact, proven R4..R12).
// Group of 4 (entry S, inputs x1..x4):
//   u1=S+x1; u2=u1+x2; u3=u2+x3              speculative no-spike FADDs
//   a  = fma(u3, [u3<=th], x4)               exact step-4 fold
//   r  = m01 ? (m0?T0:T1) : (m2?T2:a)        priority tree (first crossing)
// m0=[S>th], m01=m0|[u1>th], m2=[u2>th]; T_k = exact restart tails (helpers
// run the exact STEPX recurrence). All proven exact through R12 (rel_err 0).
//
// 32 blocks = 16 batches x 2 neuron-halves (32 chains). 256 threads:
//   wid4  : chain warp, 32 groups/tile (128 steps), exports group entries
//   wid5,6: T-table helpers for tile t+1 (even/odd groups)
//   wid1,2: rerun warps: exact per-step S of tile t-1 -> sbuf (STS.128)
//   wid3,7: drain warps: sbuf tile t-2 -> global, h-contiguous STG.128
//   wid0  : x stager (tile t+2)
// One __syncthreads per 128-step tile (256 barriers).

#define NB 16
#define NS 256
#define NH 128
#define NN 64
#define NPB 32
#define HT 128
#define NTILES 256
#define GPT 32                      // k=4 groups per tile
#define RS 132                      // sbuf row stride: 16B chunk 33n+q, conflict-free
#define TT (NS * NH)
#define TOTE ((long long)NB * NS * NN * NH)

// dynamic smem layout (float offsets)
#define OFF_TQ   0                               // float4[2][GPT][NPB] = 8192 f
#define OFF_ENT  8192                            // float [2][GPT][NPB] = 2048 f
#define OFF_SBUF (OFF_ENT + 2048)                // float [2][NPB*RS]   = 8448 f
#define OFF_XS   (OFF_SBUF + 2 * NPB * RS)       // float [4][HT]       = 512 f
#define OFF_THR  (OFF_XS + 4 * HT)               // float [NPB]         = 32 f
#define SMEM_FLOATS (OFF_THR + NPB)
#define SMEM_BYTES  (SMEM_FLOATS * 4)            // 76928 B

#define STEPX(S, XV, TH) do {                                               \
    float f_;                                                               \
    asm("set.le.f32.f32 %0, %1, %2;" : "=f"(f_) : "f"(S), "f"(TH));         \
    asm("fma.rn.f32 %0, %1, %2, %3;" : "=f"(S) : "f"(S), "f"(f_), "f"(XV)); \
} while (0)

__global__ __launch_bounds__(256, 1)
void lif_kernel(const float* __restrict__ inputs,
                const float* __restrict__ threshes,
                const float* __restrict__ acc0,
                float* __restrict__ outbuf)
{
    extern __shared__ float smem[];
    float4* const Tq   = (float4*)(smem + OFF_TQ);    // [2][GPT][NPB]
    float*  const ent  = smem + OFF_ENT;              // [2][GPT][NPB]
    float*  const sbuf = smem + OFF_SBUF;             // [2][NPB*RS]
    float*  const xs   = smem + OFF_XS;               // [4][HT]
    float*  const thr  = smem + OFF_THR;              // [NPB]

    const int b    = blockIdx.x >> 1;
    const int g    = blockIdx.x & 1;
    const int tid  = threadIdx.x;
    const int wid  = tid >> 5;
    const int lane = tid & 31;
    const float* xb = inputs + (long long)b * TT;
    float* outp = outbuf;
    float* spkp = outbuf + TOTE;

    // ---- prologue 1: stage x(0), x(1); thresholds ----
    if (wid == 0)
        *(float4*)&xs[0 * HT + lane * 4] = *(const float4*)(xb + lane * 4);
    if (wid == 3)
        *(float4*)&xs[1 * HT + lane * 4] = *(const float4*)(xb + HT + lane * 4);
    if (wid == 1) thr[lane] = threshes[g * NPB + lane];
    __syncthreads();

    const float th = thr[lane];              // lane == chain index in all roles

    // ---- prologue 2: T(0); chain loads acc0 ----
    float S = 0.0f;
    if (wid == 5 || wid == 6) {
        const int par = wid - 5;
        #pragma unroll
        for (int gg = 0; gg < 16; ++gg) {
            const int grp = gg * 2 + par;
            float4 xq = *(const float4*)&xs[0 * HT + grp * 4];
            float T2 = xq.z;  STEPX(T2, xq.w, th);
            float T1 = xq.y;  STEPX(T1, xq.z, th);  STEPX(T1, xq.w, th);
            float T0 = xq.x;  STEPX(T0, xq.y, th);  STEPX(T0, xq.z, th);
            STEPX(T0, xq.w, th);
            Tq[(0 * GPT + grp) * NPB + lane] = make_float4(T0, T1, T2, 0.0f);
        }
    }
    if (wid == 4) S = acc0[b * NN + g * NPB + lane];
    __syncthreads();

    for (int t = 0; t <= NTILES + 1; ++t) {
        if (wid == 4) {
            // ================= chain warp: tile t =================
            if (t < NTILES) {
                const float*  __restrict__ xr = xs + (t & 3) * HT;
                const float4* __restrict__ Tt = Tq + (t & 1) * GPT * NPB;
                float* __restrict__ ed = ent + (t & 1) * GPT * NPB;
                #pragma unroll
                for (int grp = 0; grp < GPT; ++grp) {
                    float4 xq = *(const float4*)&xr[grp * 4];   // broadcast LDS
                    float4 Tv = Tt[grp * NPB + lane];           // LDS.128
                    ed[grp * NPB + lane] = S;                   // group entry
                    float u1 = S + xq.x;
                    float u2 = u1 + xq.y;
                    float u3 = u2 + xq.z;
                    float Sn;
                    asm("{\n\t"
                        ".reg .pred m0, m01, m2;\n\t"
                        ".reg .f32  f3, a, sl, inr;\n\t"
                        "setp.gt.f32 m0, %1, %2;\n\t"         // S  > th
                        "setp.gt.or.f32 m01, %3, %2, m0;\n\t" // u1 > th | m0
                        "setp.gt.f32 m2, %4, %2;\n\t"         // u2 > th
                        "set.le.f32.f32 f3, %5, %2;\n\t"      // [u3 <= th]
                        "fma.rn.f32 a, %5, f3, %6;\n\t"       // exact step-4 fold
                        "selp.f32 sl, %7, %8, m0;\n\t"        // m0 ? T0 : T1
                        "selp.f32 inr, %9, a, m2;\n\t"        // m2 ? T2 : a
                        "selp.f32 %0, sl, inr, m01;\n\t"      // priority root
                        "}"
                        : "=f"(Sn)
                        : "f"(S), "f"(th), "f"(u1), "f"(u2), "f"(u3),
                          "f"(xq.w), "f"(Tv.x), "f"(Tv.y), "f"(Tv.z));
                    S = Sn;
                }
            }
        } else if (wid == 0) {
            // ================= x stager: tile t+2 =================
            if (t + 2 < NTILES)
                *(float4*)&xs[((t + 2) & 3) * HT + lane * 4] =
                    *(const float4*)(xb + (t + 2) * HT + lane * 4);
        } else if (wid == 5 || wid == 6) {
            // ================= T helpers: tile t+1 =================
            if (t + 1 < NTILES) {
                const int par = wid - 5;
                const float* __restrict__ xr = xs + ((t + 1) & 3) * HT;
                float4* __restrict__ Td = Tq + ((t + 1) & 1) * GPT * NPB;
                #pragma unroll
                for (int gg = 0; gg < 16; ++gg) {
                    const int grp = gg * 2 + par;
                    float4 xq = *(const float4*)&xr[grp * 4];
                    float T2 = xq.z;  STEPX(T2, xq.w, th);
                    float T1 = xq.y;  STEPX(T1, xq.z, th);  STEPX(T1, xq.w, th);
                    float T0 = xq.x;  STEPX(T0, xq.y, th);  STEPX(T0, xq.z, th);
                    STEPX(T0, xq.w, th);
                    Td[grp * NPB + lane] = make_float4(T0, T1, T2, 0.0f);
                }
            }
        } else if (wid == 1 || wid == 2) {
            // ================= rerun warps: tile t-1 -> sbuf =================
            if (t >= 1 && t <= NTILES) {
                const int par = wid - 1;
                const int pt  = (t - 1) & 1;
                const float* __restrict__ xr = xs + ((t - 1) & 3) * HT;
                const float* __restrict__ ed = ent + pt * GPT * NPB;
                float* __restrict__ sb = sbuf + pt * NPB * RS;
                #pragma unroll
                for (int gg = 0; gg < 16; ++gg) {
                    const int grp = gg * 2 + par;
                    float  P  = ed[grp * NPB + lane];
                    float4 xq = *(const float4*)&xr[grp * 4];
                    float4 o;
                    STEPX(P, xq.x, th); o.x = P;
                    STEPX(P, xq.y, th); o.y = P;
                    STEPX(P, xq.z, th); o.z = P;
                    STEPX(P, xq.w, th); o.w = P;
                    *(float4*)&sb[lane * RS + grp * 4] = o;    // STS.128
                }
            }
        } else {
            // ========== drain warps (wid 3,7): sbuf tile t-2 -> global ==========
            if (t >= 2) {
                const int dt = t - 2;                 // == s row (HT == NH)
                const int pt = dt & 1;
                const int idx0 = (wid == 7) ? 512 : 0;
                const float* __restrict__ sb = sbuf + pt * NPB * RS;
                float* ob = outp + (((long long)b * NS + dt) * NN + g * NPB) * NH;
                float* sp = ob + TOTE;
                #pragma unroll
                for (int i = 0; i < 16; ++i) {
                    int idx = idx0 + i * 32 + lane;   // n = idx>>5, q = idx&31
                    int n = idx >> 5, q = idx & 31;
                    float4 v = *(const float4*)&sb[n * RS + q * 4];
                    float tn = thr[n];
                    float f0, f1, f2, f3;
                    asm("set.gt.f32.f32 %0, %1, %2;" : "=f"(f0) : "f"(v.x), "f"(tn));
                    asm("set.gt.f32.f32 %0, %1, %2;" : "=f"(f1) : "f"(v.y), "f"(tn));
                    asm("set.gt.f32.f32 %0, %1, %2;" : "=f"(f2) : "f"(v.z), "f"(tn));
                    asm("set.gt.f32.f32 %0, %1, %2;" : "=f"(f3) : "f"(v.w), "f"(tn));
                    float4 o = make_float4(v.x * f0, v.y * f1, v.z * f2, v.w * f3);
                    float4 k = make_float4(f0, f1, f2, f3);
                    *(float4*)(ob + n * NH + q * 4) = o;       // STG.128 coalesced
                    *(float4*)(sp + n * NH + q * 4) = k;
                }
            }
        }
        __syncthreads();
    }
}

extern "C" void kernel_launch(void* const* d_in, const int* in_sizes, int n_in,
                              void* d_out, int out_size)
{
    const float* inputs   = (const float*)d_in[0];  // [B,S,H]
    const float* threshes = (const float*)d_in[1];  // [N]
    const float* acc0     = (const float*)d_in[2];  // [B,N]
    float* out = (float*)d_out;                     // outs then spikes (f32)

    // Raise dynamic smem ceiling (idempotent, deterministic, not a stream op
    // -> safe under graph capture; no allocation involved).
    cudaFuncSetAttribute(lif_kernel,
                         cudaFuncAttributeMaxDynamicSharedMemorySize,
                         SMEM_BYTES);
    lif_kernel<<<NB * 2, 256, SMEM_BYTES>>>(inputs, threshes, acc0, out);
}